// round 6
// baseline (speedup 1.0000x reference)
#include <cuda_runtime.h>

// TINShift: out[n,t,c,hw] = x[n, t + shift[n, c/GC], c, hw] if 0 <= t+s < T else 0
// Shapes: x [N=8, T=16, C=256, HW=3136] fp32, shift [N=8, G=8] int32.
//
// shift is constant across each contiguous 32-channel group, so the
// permutation unit is a contiguous 401408-byte slab per (n, t, group).
// Each slab (25088 float4) splits into 14 chunks of 1792 float4; one block
// per chunk (grid = 14336, ~97 blocks/SM -> ~1% imbalance). Every thread
// copies exactly 7 float4: 7 front-batched LDG.128 (MLP=7) then 7 STG.128,
// no loops / divergence / tail. Loads and stores use streaming (.cs)
// cache hints: every byte is single-touch, so evict-first minimizes L2 churn
// between the read and write streams.
//
// Design held from previous round (no measurements yet — broker timeouts);
// all structural levers for a DRAM-bound copy are already applied.

static constexpr int N  = 8;
static constexpr int T  = 16;
static constexpr int C  = 256;
static constexpr int HW = 3136;
static constexpr int G  = 8;
static constexpr int GC  = C / G;              // 32 channels per group
static constexpr int HW4 = HW / 4;             // 784 float4 per channel row
static constexpr int SLAB4 = GC * HW4;         // 25088 float4 per (n,t,g) slab
static constexpr int THREADS = 256;
static constexpr int PER_THREAD = 7;           // float4 per thread
static constexpr int CHUNK4 = THREADS * PER_THREAD;     // 1792
static constexpr int CHUNKS_PER_SLAB = SLAB4 / CHUNK4;  // 14 (exact)
static_assert(CHUNKS_PER_SLAB * CHUNK4 == SLAB4, "exact split");

__global__ __launch_bounds__(THREADS, 16)
void tin_shift_kernel(const float4* __restrict__ x4,
                      const int*    __restrict__ shift,
                      float4*       __restrict__ out4)
{
    const int blk   = blockIdx.x;                 // 0 .. N*T*G*14 - 1
    const int chunk = blk % CHUNKS_PER_SLAB;
    const int slab  = blk / CHUNKS_PER_SLAB;      // 0 .. N*T*G - 1
    const int g     = slab % G;
    const int nt    = slab / G;
    const int t     = nt % T;
    const int n     = nt / T;

    const int s     = shift[n * G + g];
    const int t_src = t + s;
    const bool valid = (t_src >= 0) && (t_src < T);

    const size_t chunk_off = (size_t)chunk * CHUNK4 + threadIdx.x;
    float4* __restrict__ dst =
        out4 + ((size_t)((n * T + t) * C + g * GC)) * HW4 + chunk_off;

    if (valid) {
        const float4* __restrict__ src =
            x4 + ((size_t)((n * T + t_src) * C + g * GC)) * HW4 + chunk_off;

        // 7 independent streaming 128-bit loads back-to-back, then 7 stores.
        float4 v0 = __ldcs(src + 0 * THREADS);
        float4 v1 = __ldcs(src + 1 * THREADS);
        float4 v2 = __ldcs(src + 2 * THREADS);
        float4 v3 = __ldcs(src + 3 * THREADS);
        float4 v4 = __ldcs(src + 4 * THREADS);
        float4 v5 = __ldcs(src + 5 * THREADS);
        float4 v6 = __ldcs(src + 6 * THREADS);
        __stcs(dst + 0 * THREADS, v0);
        __stcs(dst + 1 * THREADS, v1);
        __stcs(dst + 2 * THREADS, v2);
        __stcs(dst + 3 * THREADS, v3);
        __stcs(dst + 4 * THREADS, v4);
        __stcs(dst + 5 * THREADS, v5);
        __stcs(dst + 6 * THREADS, v6);
    } else {
        const float4 z = make_float4(0.f, 0.f, 0.f, 0.f);
        #pragma unroll
        for (int j = 0; j < PER_THREAD; ++j)
            __stcs(dst + j * THREADS, z);
    }
}

extern "C" void kernel_launch(void* const* d_in, const int* in_sizes, int n_in,
                              void* d_out, int out_size)
{
    const float4* x4    = (const float4*)d_in[0];   // x: [N,T,C,HW] fp32
    const int*    shift = (const int*)d_in[1];      // shift: [N,G] int32
    float4*       out4  = (float4*)d_out;

    tin_shift_kernel<<<N * T * G * CHUNKS_PER_SLAB, THREADS>>>(x4, shift, out4);
}